// round 16
// baseline (speedup 1.0000x reference)
#include <cuda_runtime.h>
#include <cuda_fp16.h>
#include <cuda_bf16.h>
#include <cstdint>

#define N_NODES 50000
#define N_EDGES 625000
#define C 128
#define NPART ((N_NODES + 255) / 256)   // 196 scan blocks
#define GM 64                            // GEMM rows per block
#define GBLKS ((N_NODES + GM - 1) / GM)  // 782
#define PADROWS (GBLKS * GM)             // 50048
#define NFRAG (8 * 16 * 32)              // kc16 * nt * lane = 4096

// Scratch (__device__ globals; allocations are banned)
__device__ __align__(16) __half g_yh[(size_t)PADROWS * C];  // x @ W^T, fp16
__device__ __align__(16) uint4  g_Wf[NFRAG];  // B frags: (hi0,hi1,lo0,lo1) bf16x2
__device__ float g_dis[N_NODES];             // deg^-1/2
__device__ int   g_row[N_EDGES];
__device__ int   g_col[N_EDGES];
__device__ int   g_cnt[N_NODES];             // degree counts
__device__ int   g_cur[N_NODES];             // fill cursors
__device__ int   g_off[N_NODES + 1];         // CSR offsets
__device__ int   g_ecol[N_EDGES];            // CSR column (src) ids
__device__ int   g_part[NPART];              // scan partials
__device__ int   g_is64;

// ---------------------------------------------------------------------------
static __device__ __forceinline__ void mma16(float4& d, const uint32_t* a,
                                             uint32_t b0, uint32_t b1) {
    asm volatile(
        "mma.sync.aligned.m16n8k16.row.col.f32.bf16.bf16.f32 "
        "{%0,%1,%2,%3}, {%4,%5,%6,%7}, {%8,%9}, {%0,%1,%2,%3};"
        : "+f"(d.x), "+f"(d.y), "+f"(d.z), "+f"(d.w)
        : "r"(a[0]), "r"(a[1]), "r"(a[2]), "r"(a[3]), "r"(b0), "r"(b1));
}

// Split a float pair into bf16x2 hi and bf16x2 lo (low 16 bits = first elem).
static __device__ __forceinline__ void split_bf2(float vx, float vy,
                                                 uint32_t& hi, uint32_t& lo) {
    __nv_bfloat162 h = __floats2bfloat162_rn(vx, vy);
    uint32_t u = *(uint32_t*)&h;
    float f0 = __uint_as_float(u << 16);
    float f1 = __uint_as_float(u & 0xffff0000u);
    __nv_bfloat162 l = __floats2bfloat162_rn(vx - f0, vy - f1);
    hi = u;
    lo = *(uint32_t*)&l;
}

// ---------------------------------------------------------------------------
// Fused: dtype detect (block 0) + zero counters + B-fragment pack of W.
__global__ void k_detect_prep(const long long* __restrict__ ei,
                              const float* __restrict__ W) {
    int i = blockIdx.x * blockDim.x + threadIdx.x;
    if (i < N_NODES) { g_cnt[i] = 0; g_cur[i] = 0; }
    if (i < NFRAG) {
        int lane = i & 31;
        int frag = i >> 5;
        int nt = frag & 15;
        int kc = frag >> 4;          // 0..7
        int n = nt * 8 + (lane >> 2);
        int t = lane & 3;
        int ka = kc * 16 + 2 * t;
        int kb = ka + 8;
        uint32_t h0, l0, h1, l1;
        split_bf2(W[n * C + ka], W[n * C + ka + 1], h0, l0);
        split_bf2(W[n * C + kb], W[n * C + kb + 1], h1, l1);
        g_Wf[i] = make_uint4(h0, h1, l0, l1);
    }
    if (blockIdx.x == 0) {
        __shared__ int ok;
        if (threadIdx.x == 0) ok = 1;
        __syncthreads();
        for (int s = threadIdx.x; s < 1024; s += blockDim.x) {
            long long v = ei[s];
            if (v < 0 || v >= N_NODES) atomicExch(&ok, 0);
        }
        __syncthreads();
        if (threadIdx.x == 0) g_is64 = ok;
    }
}

// normalize edges + count degrees in one pass
__global__ void k_edges(const void* __restrict__ ei) {
    int e = blockIdx.x * blockDim.x + threadIdx.x;
    if (e >= N_EDGES) return;
    int r, c;
    if (g_is64) {
        const long long* p = (const long long*)ei;
        r = (int)p[e];
        c = (int)p[e + N_EDGES];
    } else {
        const int* p = (const int*)ei;
        r = p[e];
        c = p[e + N_EDGES];
    }
    g_row[e] = r;
    g_col[e] = c;
    if ((unsigned)r < N_NODES) atomicAdd(&g_cnt[r], 1);
}

// ---------------------------------------------------------------------------
__global__ void __launch_bounds__(256) k_scan1() {
    __shared__ int s[256];
    const int t = threadIdx.x;
    const int i = blockIdx.x * 256 + t;
    s[t] = (i < N_NODES) ? g_cnt[i] : 0;
    __syncthreads();
#pragma unroll
    for (int off = 128; off > 0; off >>= 1) {
        if (t < off) s[t] += s[t + off];
        __syncthreads();
    }
    if (t == 0) g_part[blockIdx.x] = s[0];
}

__global__ void __launch_bounds__(256) k_scan_off() {
    __shared__ int sp[256];
    __shared__ int s[256];
    const int t = threadIdx.x;

    const int pv = (t < NPART) ? g_part[t] : 0;
    sp[t] = pv;
    __syncthreads();
#pragma unroll
    for (int off = 1; off < 256; off <<= 1) {
        int u = (t >= off) ? sp[t - off] : 0;
        __syncthreads();
        sp[t] += u;
        __syncthreads();
    }
    const int blk_prefix = (blockIdx.x == 0) ? 0 : sp[blockIdx.x - 1];
    if (blockIdx.x == 0 && t == 0) g_off[N_NODES] = sp[NPART - 1];

    const int i = blockIdx.x * 256 + t;
    const int v = (i < N_NODES) ? g_cnt[i] : 0;
    s[t] = v;
    __syncthreads();
#pragma unroll
    for (int off = 1; off < 256; off <<= 1) {
        int u = (t >= off) ? s[t - off] : 0;
        __syncthreads();
        s[t] += u;
        __syncthreads();
    }
    if (i < N_NODES) {
        g_off[i] = s[t] - v + blk_prefix;
        g_dis[i] = (v > 0) ? rsqrtf((float)v) : 0.f;
    }
}

__global__ void k_fill_csr() {
    int e = blockIdx.x * blockDim.x + threadIdx.x;
    if (e >= N_EDGES) return;
    unsigned r = (unsigned)g_row[e];
    unsigned c = (unsigned)g_col[e];
    if (r >= N_NODES || c >= N_NODES) return;
    int pos = g_off[r] + atomicAdd(&g_cur[r], 1);
    g_ecol[pos] = (int)c;
}

// ---------------------------------------------------------------------------
// y = x @ W^T via mma.sync m16n8k16 3xBF16.
// 512 threads = 16 warps: mg = wid>>2 (4 m-tiles), ng = wid&3 (4 n-groups).
// One m-tile per warp -> ~60 regs -> 2 CTAs/SM = 32 warps/SM latency hiding.
__global__ void __launch_bounds__(512, 2) k_gemm_mma(const float* __restrict__ x) {
    // uint2 = (hi bf16x2, lo bf16x2) per k-pair; row stride 528B (proven).
    __shared__ uint2 xhl[GM][66];

    const int tid = threadIdx.x;
    const int wid = tid >> 5, lane = tid & 31;
    const int g = lane >> 2, t = lane & 3;
    const int mg = wid >> 2;        // 0..3 -> rows mg*16 .. mg*16+15
    const int ng = wid & 3;         // 0..3 -> nt = ng*4 + ntl
    const int row0 = blockIdx.x * GM;

    // Load x tile (coalesced float4), split hi/lo once, store packed
    for (int i = tid; i < GM * 32; i += 512) {
        int r = i >> 5, q = i & 31;
        float4 v = make_float4(0.f, 0.f, 0.f, 0.f);
        if (row0 + r < N_NODES)
            v = ((const float4*)(x + (size_t)(row0 + r) * C))[q];
        uint32_t h0, l0, h1, l1;
        split_bf2(v.x, v.y, h0, l0);
        split_bf2(v.z, v.w, h1, l1);
        xhl[r][2 * q]     = make_uint2(h0, l0);
        xhl[r][2 * q + 1] = make_uint2(h1, l1);
    }
    __syncthreads();

    float4 acc[4];
#pragma unroll
    for (int n = 0; n < 4; n++) acc[n] = make_float4(0.f, 0.f, 0.f, 0.f);

    const uint4* wf = g_Wf + (size_t)(ng * 4) * 32 + lane;
    const int r0 = mg * 16 + g;

#pragma unroll
    for (int kc = 0; kc < 8; kc++) {
        const int kp = kc * 8 + t;   // k-pair index
        // B fragments first (independent LDG.128s, L1-resident)
        uint4 bf[4];
#pragma unroll
        for (int ntl = 0; ntl < 4; ntl++)
            bf[ntl] = __ldg(wf + (size_t)(kc * 16 + ntl) * 32);

        // A fragments: pure LDS.64
        uint2 u0 = xhl[r0][kp];
        uint2 u1 = xhl[r0 + 8][kp];
        uint2 u2 = xhl[r0][kp + 4];
        uint2 u3 = xhl[r0 + 8][kp + 4];
        uint32_t ah[4] = {u0.x, u1.x, u2.x, u3.x};
        uint32_t al[4] = {u0.y, u1.y, u2.y, u3.y};

#pragma unroll
        for (int ntl = 0; ntl < 4; ntl++) {
            mma16(acc[ntl], ah, bf[ntl].x, bf[ntl].y);   // hi*hi
            mma16(acc[ntl], ah, bf[ntl].z, bf[ntl].w);   // hi*lo
            mma16(acc[ntl], al, bf[ntl].x, bf[ntl].y);   // lo*hi
        }
    }

    // Epilogue: fp32 acc -> fp16; c0/c1 -> (row g, cols 2t,2t+1), c2/c3 -> row g+8
    {
        const size_t gr0 = (size_t)(row0 + r0) * C;
        const size_t gr1 = gr0 + 8 * C;
#pragma unroll
        for (int ntl = 0; ntl < 4; ntl++) {
            const int cb = (ng * 4 + ntl) * 8 + 2 * t;
            *(__half2*)&g_yh[gr0 + cb] = __floats2half2_rn(acc[ntl].x, acc[ntl].y);
            *(__half2*)&g_yh[gr1 + cb] = __floats2half2_rn(acc[ntl].z, acc[ntl].w);
        }
    }
}

// ---------------------------------------------------------------------------
// Warp per node, 2-edge unrolled; y rows read as fp16 (half L2 traffic):
// out[n] = b + dis[n] * sum_e dis[col_e] * y[col_e]
__global__ void __launch_bounds__(256) k_gather(float* __restrict__ out,
                                                const float* __restrict__ b) {
    int gtid = blockIdx.x * blockDim.x + threadIdx.x;
    int n = gtid >> 5;
    int lane = gtid & 31;
    if (n >= N_NODES) return;

    const float4 bias = __ldg(((const float4*)b) + lane);
    float ax = 0.f, ay = 0.f, az = 0.f, aw = 0.f;

    const int start = g_off[n];
    const int end = g_off[n + 1];
    const float dn = g_dis[n];

    int e = start;
    for (; e + 2 <= end; e += 2) {
        int c0 = g_ecol[e];
        int c1 = g_ecol[e + 1];
        float m0 = dn * g_dis[c0];
        float m1 = dn * g_dis[c1];
        uint2 u0 = __ldg(((const uint2*)(g_yh + (size_t)c0 * C)) + lane);
        uint2 u1 = __ldg(((const uint2*)(g_yh + (size_t)c1 * C)) + lane);
        float2 a0 = __half22float2(*(__half2*)&u0.x);
        float2 b0v = __half22float2(*(__half2*)&u0.y);
        float2 a1 = __half22float2(*(__half2*)&u1.x);
        float2 b1v = __half22float2(*(__half2*)&u1.y);
        ax += m0 * a0.x + m1 * a1.x;
        ay += m0 * a0.y + m1 * a1.y;
        az += m0 * b0v.x + m1 * b1v.x;
        aw += m0 * b0v.y + m1 * b1v.y;
    }
    if (e < end) {
        int c = g_ecol[e];
        float m = dn * g_dis[c];
        uint2 u = __ldg(((const uint2*)(g_yh + (size_t)c * C)) + lane);
        float2 a0 = __half22float2(*(__half2*)&u.x);
        float2 b0v = __half22float2(*(__half2*)&u.y);
        ax += m * a0.x;
        ay += m * a0.y;
        az += m * b0v.x;
        aw += m * b0v.y;
    }

    ((float4*)(out + (size_t)n * C))[lane] =
        make_float4(bias.x + ax, bias.y + ay, bias.z + az, bias.w + aw);
}

// ---------------------------------------------------------------------------
extern "C" void kernel_launch(void* const* d_in, const int* in_sizes, int n_in,
                              void* d_out, int out_size) {
    const float* x = (const float*)d_in[0];
    const void*  ei = d_in[1];
    const float* W = (const float*)d_in[2];
    const float* b = (const float*)d_in[3];
    float* out = (float*)d_out;

    // Fork/join: CSR chain runs on a side stream, overlapped with the GEMM.
    cudaStream_t s2;
    cudaStreamCreateWithFlags(&s2, cudaStreamNonBlocking);
    cudaEvent_t evFork, evJoin;
    cudaEventCreateWithFlags(&evFork, cudaEventDisableTiming);
    cudaEventCreateWithFlags(&evJoin, cudaEventDisableTiming);

    k_detect_prep<<<(N_NODES + 255) / 256, 256>>>((const long long*)ei, W);   // 1
    cudaEventRecord(evFork, 0);
    cudaStreamWaitEvent(s2, evFork, 0);

    k_edges<<<(N_EDGES + 255) / 256, 256, 0, s2>>>(ei);                       // 2
    k_scan1<<<NPART, 256, 0, s2>>>();                                         // 3
    k_gemm_mma<<<GBLKS, 512>>>(x);                                            // 4 (profiled)
    k_scan_off<<<NPART, 256, 0, s2>>>();                                      // 5
    k_fill_csr<<<(N_EDGES + 255) / 256, 256, 0, s2>>>();                      // 6
    cudaEventRecord(evJoin, s2);
    cudaStreamWaitEvent(0, evJoin, 0);

    const long long total = (long long)N_NODES * 32;
    k_gather<<<(int)((total + 255) / 256), 256>>>(out, b);                    // 7

    cudaEventDestroy(evFork);
    cudaEventDestroy(evJoin);
    cudaStreamDestroy(s2);
}

// round 17
// speedup vs baseline: 1.1635x; 1.1635x over previous
#include <cuda_runtime.h>
#include <cuda_fp16.h>
#include <cuda_bf16.h>
#include <cstdint>

#define N_NODES 50000
#define N_EDGES 625000
#define C 128
#define NPART ((N_NODES + 255) / 256)   // 196 scan blocks
#define GM 64                            // GEMM rows per block
#define GBLKS ((N_NODES + GM - 1) / GM)  // 782
#define PADROWS (GBLKS * GM)             // 50048
#define NFRAG (8 * 16 * 32)              // kc16 * nt * lane = 4096

// Scratch (__device__ globals; allocations are banned)
__device__ __align__(16) __half g_yh[(size_t)PADROWS * C];  // x @ W^T, fp16
__device__ __align__(16) uint2  g_Wh[NFRAG];  // B frags: (b0,b1) fp16x2
__device__ float g_dis[N_NODES];             // deg^-1/2
__device__ int   g_row[N_EDGES];
__device__ int   g_col[N_EDGES];
__device__ int   g_cnt[N_NODES];             // degree counts
__device__ int   g_cur[N_NODES];             // fill cursors
__device__ int   g_off[N_NODES + 1];         // CSR offsets
__device__ int   g_ecol[N_EDGES];            // CSR column (src) ids
__device__ int   g_part[NPART];              // scan partials
__device__ int   g_is64;

// ---------------------------------------------------------------------------
static __device__ __forceinline__ void mma16f(float4& d, const uint32_t* a,
                                              uint32_t b0, uint32_t b1) {
    asm volatile(
        "mma.sync.aligned.m16n8k16.row.col.f32.f16.f16.f32 "
        "{%0,%1,%2,%3}, {%4,%5,%6,%7}, {%8,%9}, {%0,%1,%2,%3};"
        : "+f"(d.x), "+f"(d.y), "+f"(d.z), "+f"(d.w)
        : "r"(a[0]), "r"(a[1]), "r"(a[2]), "r"(a[3]), "r"(b0), "r"(b1));
}

// ---------------------------------------------------------------------------
// Fused: dtype detect (block 0) + zero counters + fp16 B-fragment pack of W.
// m16n8k16 B frag: lane -> n = nt*8 + lane/4; b0 = {W[n][k0+2t], W[n][k0+2t+1]},
// b1 = {W[n][k0+2t+8], W[n][k0+2t+9]}, t = lane%4, k0 = kc*16.
__global__ void k_detect_prep(const long long* __restrict__ ei,
                              const float* __restrict__ W) {
    int i = blockIdx.x * blockDim.x + threadIdx.x;
    if (i < N_NODES) { g_cnt[i] = 0; g_cur[i] = 0; }
    if (i < NFRAG) {
        int lane = i & 31;
        int frag = i >> 5;
        int nt = frag & 15;
        int kc = frag >> 4;          // 0..7
        int n = nt * 8 + (lane >> 2);
        int t = lane & 3;
        int ka = kc * 16 + 2 * t;
        int kb = ka + 8;
        __half2 b0 = __floats2half2_rn(W[n * C + ka], W[n * C + ka + 1]);
        __half2 b1 = __floats2half2_rn(W[n * C + kb], W[n * C + kb + 1]);
        g_Wh[i] = make_uint2(*(uint32_t*)&b0, *(uint32_t*)&b1);
    }
    if (blockIdx.x == 0) {
        __shared__ int ok;
        if (threadIdx.x == 0) ok = 1;
        __syncthreads();
        for (int s = threadIdx.x; s < 1024; s += blockDim.x) {
            long long v = ei[s];
            if (v < 0 || v >= N_NODES) atomicExch(&ok, 0);
        }
        __syncthreads();
        if (threadIdx.x == 0) g_is64 = ok;
    }
}

// normalize edges + count degrees in one pass
__global__ void k_edges(const void* __restrict__ ei) {
    int e = blockIdx.x * blockDim.x + threadIdx.x;
    if (e >= N_EDGES) return;
    int r, c;
    if (g_is64) {
        const long long* p = (const long long*)ei;
        r = (int)p[e];
        c = (int)p[e + N_EDGES];
    } else {
        const int* p = (const int*)ei;
        r = p[e];
        c = p[e + N_EDGES];
    }
    g_row[e] = r;
    g_col[e] = c;
    if ((unsigned)r < N_NODES) atomicAdd(&g_cnt[r], 1);
}

// ---------------------------------------------------------------------------
__global__ void __launch_bounds__(256) k_scan1() {
    __shared__ int s[256];
    const int t = threadIdx.x;
    const int i = blockIdx.x * 256 + t;
    s[t] = (i < N_NODES) ? g_cnt[i] : 0;
    __syncthreads();
#pragma unroll
    for (int off = 128; off > 0; off >>= 1) {
        if (t < off) s[t] += s[t + off];
        __syncthreads();
    }
    if (t == 0) g_part[blockIdx.x] = s[0];
}

__global__ void __launch_bounds__(256) k_scan_off() {
    __shared__ int sp[256];
    __shared__ int s[256];
    const int t = threadIdx.x;

    const int pv = (t < NPART) ? g_part[t] : 0;
    sp[t] = pv;
    __syncthreads();
#pragma unroll
    for (int off = 1; off < 256; off <<= 1) {
        int u = (t >= off) ? sp[t - off] : 0;
        __syncthreads();
        sp[t] += u;
        __syncthreads();
    }
    const int blk_prefix = (blockIdx.x == 0) ? 0 : sp[blockIdx.x - 1];
    if (blockIdx.x == 0 && t == 0) g_off[N_NODES] = sp[NPART - 1];

    const int i = blockIdx.x * 256 + t;
    const int v = (i < N_NODES) ? g_cnt[i] : 0;
    s[t] = v;
    __syncthreads();
#pragma unroll
    for (int off = 1; off < 256; off <<= 1) {
        int u = (t >= off) ? s[t - off] : 0;
        __syncthreads();
        s[t] += u;
        __syncthreads();
    }
    if (i < N_NODES) {
        g_off[i] = s[t] - v + blk_prefix;
        g_dis[i] = (v > 0) ? rsqrtf((float)v) : 0.f;
    }
}

__global__ void k_fill_csr() {
    int e = blockIdx.x * blockDim.x + threadIdx.x;
    if (e >= N_EDGES) return;
    unsigned r = (unsigned)g_row[e];
    unsigned c = (unsigned)g_col[e];
    if (r >= N_NODES || c >= N_NODES) return;
    int pos = g_off[r] + atomicAdd(&g_cur[r], 1);
    g_ecol[pos] = (int)c;
}

// ---------------------------------------------------------------------------
// y = x @ W^T via mma.sync m16n8k16 fp16 single-pass (x,W rounded to fp16;
// fp32 accum). 1/3 the MMA count of the 3xBF16 version — MMA-issue-bound.
// 256 threads = 8 warps: mg = wid>>2 (2 m-tile pairs), ng = wid&3.
__global__ void __launch_bounds__(256, 2) k_gemm_mma(const float* __restrict__ x) {
    // half2 per k-pair; row stride 68 words -> A-frag banks (4g+t): conflict-free.
    __shared__ uint32_t xh[GM][68];

    const int tid = threadIdx.x;
    const int wid = tid >> 5, lane = tid & 31;
    const int g = lane >> 2, t = lane & 3;
    const int mg = wid >> 2;        // 0..1  -> rows mg*32 + mt*16
    const int ng = wid & 3;         // 0..3  -> nt = ng*4 + ntl
    const int row0 = blockIdx.x * GM;

    // Load x tile (coalesced float4), convert to fp16x2 pairs
    for (int i = tid; i < GM * 32; i += 256) {
        int r = i >> 5, q = i & 31;
        float4 v = make_float4(0.f, 0.f, 0.f, 0.f);
        if (row0 + r < N_NODES)
            v = ((const float4*)(x + (size_t)(row0 + r) * C))[q];
        __half2 h0 = __floats2half2_rn(v.x, v.y);
        __half2 h1 = __floats2half2_rn(v.z, v.w);
        xh[r][2 * q]     = *(uint32_t*)&h0;
        xh[r][2 * q + 1] = *(uint32_t*)&h1;
    }
    __syncthreads();

    float4 acc[2][4];
#pragma unroll
    for (int mt = 0; mt < 2; mt++)
#pragma unroll
        for (int n = 0; n < 4; n++) acc[mt][n] = make_float4(0.f, 0.f, 0.f, 0.f);

    const uint2* wf = g_Wh + (size_t)(ng * 4) * 32 + lane;

#pragma unroll
    for (int kc = 0; kc < 8; kc++) {
        const int kp = kc * 8 + t;   // k-pair index
        // B fragments (independent LDG.64s, L1-resident)
        uint2 bf[4];
#pragma unroll
        for (int ntl = 0; ntl < 4; ntl++)
            bf[ntl] = __ldg(wf + (size_t)(kc * 16 + ntl) * 32);

        // A fragments: pure LDS.32, conflict-free
        uint32_t a[2][4];
#pragma unroll
        for (int mt = 0; mt < 2; mt++) {
            const int r0 = mg * 32 + mt * 16 + g;
            a[mt][0] = xh[r0][kp];
            a[mt][1] = xh[r0 + 8][kp];
            a[mt][2] = xh[r0][kp + 4];
            a[mt][3] = xh[r0 + 8][kp + 4];
        }
#pragma unroll
        for (int ntl = 0; ntl < 4; ntl++)
#pragma unroll
            for (int mt = 0; mt < 2; mt++)
                mma16f(acc[mt][ntl], a[mt], bf[ntl].x, bf[ntl].y);
    }

    // Epilogue: fp32 acc -> fp16; c0/c1 -> (row g, cols 2t,2t+1), c2/c3 -> row g+8
#pragma unroll
    for (int mt = 0; mt < 2; mt++) {
        const size_t gr0 = (size_t)(row0 + mg * 32 + mt * 16 + g) * C;
        const size_t gr1 = gr0 + 8 * C;
#pragma unroll
        for (int ntl = 0; ntl < 4; ntl++) {
            const int cb = (ng * 4 + ntl) * 8 + 2 * t;
            *(__half2*)&g_yh[gr0 + cb] = __floats2half2_rn(acc[mt][ntl].x, acc[mt][ntl].y);
            *(__half2*)&g_yh[gr1 + cb] = __floats2half2_rn(acc[mt][ntl].z, acc[mt][ntl].w);
        }
    }
}

// ---------------------------------------------------------------------------
// Warp per node, 2-edge unrolled; y rows read as fp16 (half L2 traffic):
// out[n] = b + dis[n] * sum_e dis[col_e] * y[col_e]
__global__ void __launch_bounds__(256) k_gather(float* __restrict__ out,
                                                const float* __restrict__ b) {
    int gtid = blockIdx.x * blockDim.x + threadIdx.x;
    int n = gtid >> 5;
    int lane = gtid & 31;
    if (n >= N_NODES) return;

    const float4 bias = __ldg(((const float4*)b) + lane);
    float ax = 0.f, ay = 0.f, az = 0.f, aw = 0.f;

    const int start = g_off[n];
    const int end = g_off[n + 1];
    const float dn = g_dis[n];

    int e = start;
    for (; e + 2 <= end; e += 2) {
        int c0 = g_ecol[e];
        int c1 = g_ecol[e + 1];
        float m0 = dn * g_dis[c0];
        float m1 = dn * g_dis[c1];
        uint2 u0 = __ldg(((const uint2*)(g_yh + (size_t)c0 * C)) + lane);
        uint2 u1 = __ldg(((const uint2*)(g_yh + (size_t)c1 * C)) + lane);
        float2 a0 = __half22float2(*(__half2*)&u0.x);
        float2 b0v = __half22float2(*(__half2*)&u0.y);
        float2 a1 = __half22float2(*(__half2*)&u1.x);
        float2 b1v = __half22float2(*(__half2*)&u1.y);
        ax += m0 * a0.x + m1 * a1.x;
        ay += m0 * a0.y + m1 * a1.y;
        az += m0 * b0v.x + m1 * b1v.x;
        aw += m0 * b0v.y + m1 * b1v.y;
    }
    if (e < end) {
        int c = g_ecol[e];
        float m = dn * g_dis[c];
        uint2 u = __ldg(((const uint2*)(g_yh + (size_t)c * C)) + lane);
        float2 a0 = __half22float2(*(__half2*)&u.x);
        float2 b0v = __half22float2(*(__half2*)&u.y);
        ax += m * a0.x;
        ay += m * a0.y;
        az += m * b0v.x;
        aw += m * b0v.y;
    }

    ((float4*)(out + (size_t)n * C))[lane] =
        make_float4(bias.x + ax, bias.y + ay, bias.z + az, bias.w + aw);
}

// ---------------------------------------------------------------------------
extern "C" void kernel_launch(void* const* d_in, const int* in_sizes, int n_in,
                              void* d_out, int out_size) {
    const float* x = (const float*)d_in[0];
    const void*  ei = d_in[1];
    const float* W = (const float*)d_in[2];
    const float* b = (const float*)d_in[3];
    float* out = (float*)d_out;

    // Fork/join: CSR chain runs on a side stream, overlapped with the GEMM.
    cudaStream_t s2;
    cudaStreamCreateWithFlags(&s2, cudaStreamNonBlocking);
    cudaEvent_t evFork, evJoin;
    cudaEventCreateWithFlags(&evFork, cudaEventDisableTiming);
    cudaEventCreateWithFlags(&evJoin, cudaEventDisableTiming);

    k_detect_prep<<<(N_NODES + 255) / 256, 256>>>((const long long*)ei, W);   // 1
    cudaEventRecord(evFork, 0);
    cudaStreamWaitEvent(s2, evFork, 0);

    k_edges<<<(N_EDGES + 255) / 256, 256, 0, s2>>>(ei);                       // 2
    k_scan1<<<NPART, 256, 0, s2>>>();                                         // 3
    k_gemm_mma<<<GBLKS, 256>>>(x);                                            // 4 (profiled)
    k_scan_off<<<NPART, 256, 0, s2>>>();                                      // 5
    k_fill_csr<<<(N_EDGES + 255) / 256, 256, 0, s2>>>();                      // 6
    cudaEventRecord(evJoin, s2);
    cudaStreamWaitEvent(0, evJoin, 0);

    const long long total = (long long)N_NODES * 32;
    k_gather<<<(int)((total + 255) / 256), 256>>>(out, b);                    // 7

    cudaEventDestroy(evFork);
    cudaEventDestroy(evJoin);
    cudaStreamDestroy(s2);
}